// round 1
// baseline (speedup 1.0000x reference)
#include <cuda_runtime.h>

#define NN  100000
#define EE  1000000
#define IND 128
#define HID 256
#define GG  64
#define BN_EPS 1e-5f

// ---------------- scratch (static device globals; no allocation) ----------------
__device__ float g_agg[NN * IND];            // 51.2 MB   neighbor feature sums
__device__ int   g_deg[NN];                  // in-degree counts
__device__ float g_h[NN * HID];              // 102.4 MB  relu(conv) output
__device__ float g_pooled[GG * HID];         // per-graph sum-pool
// g_bnstats layout (each 256 floats):
// [0]=colsum [1]=colsumsq [2]=s1 [3]=s1sq [4]=s2 [5]=s2sq [6]=scale [7]=shift
__device__ float g_bnstats[8 * HID];
__device__ float g_z1[GG * HID];
__device__ float g_z2[GG * HID];
__device__ float g_p[GG * HID];              // fallback p storage if out_size small

// ---------------- helpers ----------------
__device__ __forceinline__ unsigned long long pack2(float lo, float hi) {
    unsigned long long r;
    asm("mov.b64 %0, {%1, %2};" : "=l"(r) : "f"(lo), "f"(hi));
    return r;
}
__device__ __forceinline__ float2 unpack2(unsigned long long v) {
    float2 f;
    asm("mov.b64 {%0, %1}, %2;" : "=f"(f.x), "=f"(f.y) : "l"(v));
    return f;
}
// packed f32x2 FMA: acc += a * b (two fp32 lanes per instruction)
__device__ __forceinline__ void fma2(unsigned long long& acc, unsigned long long a,
                                     unsigned long long b) {
    asm("fma.rn.f32x2 %0, %1, %2, %0;" : "+l"(acc) : "l"(a), "l"(b));
}
// vector float4 reduction to global (no return value)
__device__ __forceinline__ void redF4(float4* addr, float4 v) {
    asm volatile("red.global.add.v4.f32 [%0], {%1, %2, %3, %4};"
                 :: "l"(addr), "f"(v.x), "f"(v.y), "f"(v.z), "f"(v.w)
                 : "memory");
}

// ---------------- K0: zero scratch ----------------
__global__ void zero_kernel() {
    int idx = blockIdx.x * blockDim.x + threadIdx.x;
    if (idx < NN * IND / 4)
        ((float4*)g_agg)[idx] = make_float4(0.f, 0.f, 0.f, 0.f);
    if (idx < NN) g_deg[idx] = 0;
    if (idx < GG * HID) g_pooled[idx] = 0.f;
    if (idx < 6 * HID) g_bnstats[idx] = 0.f;
}

// ---------------- K1: edge gather + scatter-add (warp per edge) ----------------
__global__ void scatter_kernel(const float* __restrict__ feat,
                               const int* __restrict__ src,
                               const int* __restrict__ dst) {
    int t = blockIdx.x * blockDim.x + threadIdx.x;
    int e = t >> 5;
    if (e >= EE) return;
    int lane = t & 31;
    int s = __ldg(&src[e]);
    int d = __ldg(&dst[e]);
    float4 v = __ldg(((const float4*)(feat + (size_t)s * IND)) + lane);
    redF4(((float4*)(g_agg + (size_t)d * IND)) + lane, v);
    if (lane == 0) atomicAdd(&g_deg[d], 1);
}

// ---------------- K2: fused GEMM  h = relu([feat | agg/deg] @ [Wself;Wneigh] + b)
//                      + BN column statistics ----------------
__global__ __launch_bounds__(256, 2) void conv_gemm_kernel(
    const float* __restrict__ feat, const float* __restrict__ W_self,
    const float* __restrict__ W_neigh, const float* __restrict__ b_conv) {
    __shared__ float As[32][72];    // A tile, transposed [k][row], padded
    __shared__ float Ws[32][256];   // W tile [k][col]  (reused for BN reduce)
    __shared__ float invd[64];
    __shared__ float bsh[256];

    int tid = threadIdx.x;
    int row0 = blockIdx.x * 64;
    bsh[tid] = b_conv[tid];
    if (tid < 64) {
        int node = row0 + tid;
        float dg = (node < NN) ? fmaxf((float)g_deg[node], 1.f) : 1.f;
        invd[tid] = 1.f / dg;
    }
    int ty = tid >> 5;   // row group (8)
    int tx = tid & 31;   // col group (32)

    unsigned long long acc[8][4];
#pragma unroll
    for (int r = 0; r < 8; r++)
#pragma unroll
        for (int c = 0; c < 4; c++) acc[r][c] = 0ull;

    for (int kc = 0; kc < 8; kc++) {
        int k0 = kc * 32;
        __syncthreads();
        // A tile: 64 rows x 32 k, stored transposed
#pragma unroll
        for (int i = 0; i < 2; i++) {
            int idx = tid + i * 256;
            int row = idx >> 3, kq = idx & 7;
            int node = row0 + row;
            int k = k0 + kq * 4;
            float4 v = make_float4(0.f, 0.f, 0.f, 0.f);
            if (node < NN) {
                if (k < IND) {
                    v = *(const float4*)(feat + (size_t)node * IND + k);
                } else {
                    v = *(const float4*)(g_agg + (size_t)node * IND + (k - IND));
                    float s0 = invd[row];
                    v.x *= s0; v.y *= s0; v.z *= s0; v.w *= s0;
                }
            }
            As[kq * 4 + 0][row] = v.x;
            As[kq * 4 + 1][row] = v.y;
            As[kq * 4 + 2][row] = v.z;
            As[kq * 4 + 3][row] = v.w;
        }
        // W tile: 32 k x 256 cols
#pragma unroll
        for (int i = 0; i < 8; i++) {
            int idx = tid + i * 256;
            int kk = idx >> 6, c4 = idx & 63;
            int k = k0 + kk;
            const float* w = (k < IND) ? (W_self + (size_t)k * HID + c4 * 4)
                                       : (W_neigh + (size_t)(k - IND) * HID + c4 * 4);
            *(float4*)&Ws[kk][c4 * 4] = *(const float4*)w;
        }
        __syncthreads();
#pragma unroll 8
        for (int kk = 0; kk < 32; kk++) {
            float4 a0 = *(const float4*)&As[kk][ty * 8];
            float4 a1 = *(const float4*)&As[kk][ty * 8 + 4];
            float4 w0 = *(const float4*)&Ws[kk][tx * 8];
            float4 w1 = *(const float4*)&Ws[kk][tx * 8 + 4];
            unsigned long long wp0 = pack2(w0.x, w0.y);
            unsigned long long wp1 = pack2(w0.z, w0.w);
            unsigned long long wp2 = pack2(w1.x, w1.y);
            unsigned long long wp3 = pack2(w1.z, w1.w);
            float ar[8] = {a0.x, a0.y, a0.z, a0.w, a1.x, a1.y, a1.z, a1.w};
#pragma unroll
            for (int r = 0; r < 8; r++) {
                unsigned long long ad = pack2(ar[r], ar[r]);
                fma2(acc[r][0], ad, wp0);
                fma2(acc[r][1], ad, wp1);
                fma2(acc[r][2], ad, wp2);
                fma2(acc[r][3], ad, wp3);
            }
        }
    }
    __syncthreads();

    // epilogue: bias + relu, store, local BN stats
    float csum[8], csq[8];
#pragma unroll
    for (int j = 0; j < 8; j++) { csum[j] = 0.f; csq[j] = 0.f; }
#pragma unroll
    for (int r = 0; r < 8; r++) {
        int node = row0 + ty * 8 + r;
        if (node < NN) {
            float hv[8];
#pragma unroll
            for (int c2 = 0; c2 < 4; c2++) {
                float2 v = unpack2(acc[r][c2]);
                hv[c2 * 2]     = fmaxf(v.x + bsh[tx * 8 + c2 * 2], 0.f);
                hv[c2 * 2 + 1] = fmaxf(v.y + bsh[tx * 8 + c2 * 2 + 1], 0.f);
            }
            float4* o = (float4*)(g_h + (size_t)node * HID + tx * 8);
            o[0] = make_float4(hv[0], hv[1], hv[2], hv[3]);
            o[1] = make_float4(hv[4], hv[5], hv[6], hv[7]);
#pragma unroll
            for (int j = 0; j < 8; j++) { csum[j] += hv[j]; csq[j] += hv[j] * hv[j]; }
        }
    }
    // block-level column reduction through smem (reuse Ws), then 2 atomics/col
    float* red = &Ws[0][0];
#pragma unroll
    for (int j = 0; j < 8; j++) red[ty * 264 + tx * 8 + j] = csum[j];
    __syncthreads();
    {
        float s = 0.f;
#pragma unroll
        for (int t = 0; t < 8; t++) s += red[t * 264 + tid];
        atomicAdd(&g_bnstats[tid], s);
    }
    __syncthreads();
#pragma unroll
    for (int j = 0; j < 8; j++) red[ty * 264 + tx * 8 + j] = csq[j];
    __syncthreads();
    {
        float q = 0.f;
#pragma unroll
        for (int t = 0; t < 8; t++) q += red[t * 264 + tid];
        atomicAdd(&g_bnstats[256 + tid], q);
    }
}

// ---------------- K2b: fold BN stats into per-column scale/shift ----------------
__global__ void bn_scale_kernel(const float* __restrict__ gamma,
                                const float* __restrict__ beta) {
    int c = threadIdx.x;
    float mean = g_bnstats[c] * (1.0f / NN);
    float var  = g_bnstats[256 + c] * (1.0f / NN) - mean * mean;
    float sc = gamma[c] * rsqrtf(var + BN_EPS);
    g_bnstats[1536 + c] = sc;
    g_bnstats[1792 + c] = beta[c] - mean * sc;
}

// ---------------- K3: BN apply + per-graph sum pooling ----------------
__global__ void bn_pool_kernel(const int* __restrict__ graph_id) {
    int idx = blockIdx.x * blockDim.x + threadIdx.x;
    if (idx >= NN * (HID / 4)) return;
    int node = idx >> 6;
    int c4 = idx & 63;
    float4 h = ((const float4*)(g_h + (size_t)node * HID))[c4];
    float4 sc = ((const float4*)(g_bnstats + 1536))[c4];
    float4 sh = ((const float4*)(g_bnstats + 1792))[c4];
    float4 v;
    v.x = fmaf(h.x, sc.x, sh.x);
    v.y = fmaf(h.y, sc.y, sh.y);
    v.z = fmaf(h.z, sc.z, sh.z);
    v.w = fmaf(h.w, sc.w, sh.w);
    int g = __ldg(&graph_id[node]);
    redF4(((float4*)(g_pooled + g * HID)) + c4, v);
}

// ---------------- K4: head pass 1  z1 = relu(pooled @ W_lp + b) + stats ----------------
__global__ __launch_bounds__(HID) void lp1_kernel(const float* __restrict__ W_lp,
                                                  const float* __restrict__ b_lp) {
    __shared__ float row[HID];
    int g = blockIdx.x, c = threadIdx.x;
    row[c] = g_pooled[g * HID + c];
    __syncthreads();
    float acc = b_lp[c];
#pragma unroll 8
    for (int k = 0; k < HID; k++) acc = fmaf(row[k], __ldg(&W_lp[k * HID + c]), acc);
    float r = fmaxf(acc, 0.f);
    g_z1[g * HID + c] = r;
    atomicAdd(&g_bnstats[512 + c], r);
    atomicAdd(&g_bnstats[768 + c], r * r);
}

// ---------------- K5: BN(z1) -> p (output), then z2 = relu(p @ W_lp + b) + stats ----
__global__ __launch_bounds__(HID) void lp2_kernel(const float* __restrict__ W_lp,
                                                  const float* __restrict__ b_lp,
                                                  const float* __restrict__ gamma,
                                                  const float* __restrict__ beta,
                                                  float* __restrict__ out_p) {
    __shared__ float row[HID];
    int g = blockIdx.x, c = threadIdx.x;
    float r = g_z1[g * HID + c];
    float mean = g_bnstats[512 + c] * (1.f / GG);
    float var  = g_bnstats[768 + c] * (1.f / GG) - mean * mean;
    float p = (r - mean) * rsqrtf(var + BN_EPS) * gamma[c] + beta[c];
    out_p[g * HID + c] = p;
    row[c] = p;
    __syncthreads();
    float acc = b_lp[c];
#pragma unroll 8
    for (int k = 0; k < HID; k++) acc = fmaf(row[k], __ldg(&W_lp[k * HID + c]), acc);
    float r2 = fmaxf(acc, 0.f);
    g_z2[g * HID + c] = r2;
    atomicAdd(&g_bnstats[1024 + c], r2);
    atomicAdd(&g_bnstats[1280 + c], r2 * r2);
}

// ---------------- K6: BN(z2) + log_softmax -> output ----------------
__global__ __launch_bounds__(HID) void lp3_kernel(const float* __restrict__ gamma,
                                                  const float* __restrict__ beta,
                                                  float* __restrict__ out) {
    __shared__ float buf[HID];
    int g = blockIdx.x, c = threadIdx.x;
    float r = g_z2[g * HID + c];
    float mean = g_bnstats[1024 + c] * (1.f / GG);
    float var  = g_bnstats[1280 + c] * (1.f / GG) - mean * mean;
    float o = (r - mean) * rsqrtf(var + BN_EPS) * gamma[c] + beta[c];
    buf[c] = o;
    __syncthreads();
    for (int s = 128; s > 0; s >>= 1) {
        if (c < s) buf[c] = fmaxf(buf[c], buf[c + s]);
        __syncthreads();
    }
    float m = buf[0];
    __syncthreads();
    float e = expf(o - m);
    buf[c] = e;
    __syncthreads();
    for (int s = 128; s > 0; s >>= 1) {
        if (c < s) buf[c] += buf[c + s];
        __syncthreads();
    }
    float lse = logf(buf[0]);
    out[g * HID + c] = o - m - lse;
}

// ---------------- launch ----------------
extern "C" void kernel_launch(void* const* d_in, const int* in_sizes, int n_in,
                              void* d_out, int out_size) {
    const float* feat       = (const float*)d_in[0];
    const float* W_self     = (const float*)d_in[1];
    const float* W_neigh    = (const float*)d_in[2];
    const float* b_conv     = (const float*)d_in[3];
    const float* gamma_conv = (const float*)d_in[4];
    const float* beta_conv  = (const float*)d_in[5];
    const float* W_lp       = (const float*)d_in[6];
    const float* b_lp       = (const float*)d_in[7];
    const float* gamma_lp   = (const float*)d_in[8];
    const float* beta_lp    = (const float*)d_in[9];
    const int*   src        = (const int*)d_in[10];
    const int*   dst        = (const int*)d_in[11];
    const int*   graph_id   = (const int*)d_in[12];
    float* out = (float*)d_out;

    // where to write p (second tuple element); fall back to scratch if the
    // harness output only holds the first element
    float* out_p;
    if (out_size >= 2 * GG * HID) {
        out_p = out + GG * HID;
    } else {
        void* pp = nullptr;
        cudaGetSymbolAddress(&pp, g_p);
        out_p = (float*)pp;
    }

    zero_kernel<<<(NN * IND / 4 + 255) / 256, 256>>>();
    scatter_kernel<<<(EE * 32 + 255) / 256, 256>>>(feat, src, dst);
    conv_gemm_kernel<<<(NN + 63) / 64, 256>>>(feat, W_self, W_neigh, b_conv);
    bn_scale_kernel<<<1, HID>>>(gamma_conv, beta_conv);
    bn_pool_kernel<<<(NN * (HID / 4) + 255) / 256, 256>>>(graph_id);
    lp1_kernel<<<GG, HID>>>(W_lp, b_lp);
    lp2_kernel<<<GG, HID>>>(W_lp, b_lp, gamma_lp, beta_lp, out_p);
    lp3_kernel<<<GG, HID>>>(gamma_lp, beta_lp, out);
}

// round 2
// speedup vs baseline: 1.2990x; 1.2990x over previous
#include <cuda_runtime.h>

#define NN  100000
#define EE  1000000
#define IND 128
#define HID 256
#define GG  64
#define BN_EPS 1e-5f

// ---------------- scratch (static device globals; no allocation) ----------------
__device__ float g_agg[NN * IND];            // 51.2 MB   neighbor feature sums
__device__ int   g_deg[NN];                  // in-degree counts
__device__ float g_poolraw[GG * HID];        // per-graph sums of relu(conv), pre-BN
__device__ int   g_cnt[GG];                  // nodes per graph
// g_bnstats layout (each 256 floats):
// [0]=colsum [1]=colsumsq [2]=s1 [3]=s1sq [4]=s2 [5]=s2sq [6]=scale [7]=shift
__device__ float g_bnstats[8 * HID];
__device__ float g_z1[GG * HID];
__device__ float g_z2[GG * HID];
__device__ float g_p[GG * HID];              // fallback p storage if out_size small

// ---------------- helpers ----------------
__device__ __forceinline__ unsigned long long pack2(float lo, float hi) {
    unsigned long long r;
    asm("mov.b64 %0, {%1, %2};" : "=l"(r) : "f"(lo), "f"(hi));
    return r;
}
__device__ __forceinline__ float2 unpack2(unsigned long long v) {
    float2 f;
    asm("mov.b64 {%0, %1}, %2;" : "=f"(f.x), "=f"(f.y) : "l"(v));
    return f;
}
// packed f32x2 FMA: acc += a * b (two fp32 lanes per instruction)
__device__ __forceinline__ void fma2(unsigned long long& acc, unsigned long long a,
                                     unsigned long long b) {
    asm("fma.rn.f32x2 %0, %1, %2, %0;" : "+l"(acc) : "l"(a), "l"(b));
}
// vector float4 reduction to global (no return value)
__device__ __forceinline__ void redF4(float4* addr, float4 v) {
    asm volatile("red.global.add.v4.f32 [%0], {%1, %2, %3, %4};"
                 :: "l"(addr), "f"(v.x), "f"(v.y), "f"(v.z), "f"(v.w)
                 : "memory");
}
__device__ __forceinline__ void redF1(float* addr, float v) {
    asm volatile("red.global.add.f32 [%0], %1;" :: "l"(addr), "f"(v) : "memory");
}

// ---------------- K0: zero scratch ----------------
__global__ void zero_kernel() {
    int idx = blockIdx.x * blockDim.x + threadIdx.x;
    if (idx < NN * IND / 4)
        ((float4*)g_agg)[idx] = make_float4(0.f, 0.f, 0.f, 0.f);
    if (idx < NN) g_deg[idx] = 0;
    if (idx < GG * HID) g_poolraw[idx] = 0.f;
    if (idx < GG) g_cnt[idx] = 0;
    if (idx < 6 * HID) g_bnstats[idx] = 0.f;
}

// ---------------- K0b: per-graph node counts (smem pre-aggregated) ----------------
__global__ void count_kernel(const int* __restrict__ graph_id) {
    __shared__ int cnt[GG];
    int t = threadIdx.x;
    if (t < GG) cnt[t] = 0;
    __syncthreads();
    for (int i = blockIdx.x * blockDim.x + t; i < NN; i += gridDim.x * blockDim.x)
        atomicAdd(&cnt[__ldg(&graph_id[i])], 1);
    __syncthreads();
    if (t < GG && cnt[t]) atomicAdd(&g_cnt[t], cnt[t]);
}

// ---------------- K1: edge gather + scatter-add (warp per edge) ----------------
__global__ void scatter_kernel(const float* __restrict__ feat,
                               const int* __restrict__ src,
                               const int* __restrict__ dst) {
    int t = blockIdx.x * blockDim.x + threadIdx.x;
    int e = t >> 5;
    if (e >= EE) return;
    int lane = t & 31;
    int s = __ldg(&src[e]);
    int d = __ldg(&dst[e]);
    float4 v = __ldg(((const float4*)(feat + (size_t)s * IND)) + lane);
    redF4(((float4*)(g_agg + (size_t)d * IND)) + lane, v);
    if (lane == 0) atomicAdd(&g_deg[d], 1);
}

// ---------------- K2: fused GEMM  h = relu([feat | agg/deg] @ [Wself;Wneigh] + b)
//                 + BN column statistics + per-graph raw pooling ----------------
__global__ __launch_bounds__(256, 2) void conv_gemm_kernel(
    const float* __restrict__ feat, const float* __restrict__ W_self,
    const float* __restrict__ W_neigh, const float* __restrict__ b_conv,
    const int* __restrict__ graph_id) {
    __shared__ float As[32][72];    // A tile, transposed [k][row], padded
    __shared__ float Ws[32][256];   // W tile [k][col]  (reused for reductions)
    __shared__ float invd[64];
    __shared__ float bsh[256];
    __shared__ int   gids[64];
    __shared__ int   grange[2];

    int tid = threadIdx.x;
    int row0 = blockIdx.x * 64;
    bsh[tid] = b_conv[tid];
    if (tid < 64) {
        int node = row0 + tid;
        float dg = 1.f;
        int gid = -1;
        if (node < NN) {
            dg = fmaxf((float)g_deg[node], 1.f);
            gid = __ldg(&graph_id[node]);
        }
        invd[tid] = 1.f / dg;
        gids[tid] = gid;
    }
    int ty = tid >> 5;   // row group (8)
    int tx = tid & 31;   // col group (32)

    unsigned long long acc[8][4];
#pragma unroll
    for (int r = 0; r < 8; r++)
#pragma unroll
        for (int c = 0; c < 4; c++) acc[r][c] = 0ull;

    for (int kc = 0; kc < 8; kc++) {
        int k0 = kc * 32;
        __syncthreads();
        // A tile: 64 rows x 32 k, stored transposed
#pragma unroll
        for (int i = 0; i < 2; i++) {
            int idx = tid + i * 256;
            int row = idx >> 3, kq = idx & 7;
            int node = row0 + row;
            int k = k0 + kq * 4;
            float4 v = make_float4(0.f, 0.f, 0.f, 0.f);
            if (node < NN) {
                if (k < IND) {
                    v = *(const float4*)(feat + (size_t)node * IND + k);
                } else {
                    v = *(const float4*)(g_agg + (size_t)node * IND + (k - IND));
                    float s0 = invd[row];
                    v.x *= s0; v.y *= s0; v.z *= s0; v.w *= s0;
                }
            }
            As[kq * 4 + 0][row] = v.x;
            As[kq * 4 + 1][row] = v.y;
            As[kq * 4 + 2][row] = v.z;
            As[kq * 4 + 3][row] = v.w;
        }
        // W tile: 32 k x 256 cols
#pragma unroll
        for (int i = 0; i < 8; i++) {
            int idx = tid + i * 256;
            int kk = idx >> 6, c4 = idx & 63;
            int k = k0 + kk;
            const float* w = (k < IND) ? (W_self + (size_t)k * HID + c4 * 4)
                                       : (W_neigh + (size_t)(k - IND) * HID + c4 * 4);
            *(float4*)&Ws[kk][c4 * 4] = *(const float4*)w;
        }
        __syncthreads();
#pragma unroll 8
        for (int kk = 0; kk < 32; kk++) {
            float4 a0 = *(const float4*)&As[kk][ty * 8];
            float4 a1 = *(const float4*)&As[kk][ty * 8 + 4];
            float4 w0 = *(const float4*)&Ws[kk][tx * 8];
            float4 w1 = *(const float4*)&Ws[kk][tx * 8 + 4];
            unsigned long long wp0 = pack2(w0.x, w0.y);
            unsigned long long wp1 = pack2(w0.z, w0.w);
            unsigned long long wp2 = pack2(w1.x, w1.y);
            unsigned long long wp3 = pack2(w1.z, w1.w);
            float ar[8] = {a0.x, a0.y, a0.z, a0.w, a1.x, a1.y, a1.z, a1.w};
#pragma unroll
            for (int r = 0; r < 8; r++) {
                unsigned long long ad = pack2(ar[r], ar[r]);
                fma2(acc[r][0], ad, wp0);
                fma2(acc[r][1], ad, wp1);
                fma2(acc[r][2], ad, wp2);
                fma2(acc[r][3], ad, wp3);
            }
        }
    }
    __syncthreads();

    // epilogue: bias + relu into hv (kept in regs), BN stats, per-graph pooling
    float hv[8][8];
    float csum[8], csq[8];
#pragma unroll
    for (int j = 0; j < 8; j++) { csum[j] = 0.f; csq[j] = 0.f; }
#pragma unroll
    for (int r = 0; r < 8; r++) {
        int node = row0 + ty * 8 + r;
        bool valid = (node < NN);
#pragma unroll
        for (int c2 = 0; c2 < 4; c2++) {
            float2 v = unpack2(acc[r][c2]);
            float h0 = fmaxf(v.x + bsh[tx * 8 + c2 * 2], 0.f);
            float h1 = fmaxf(v.y + bsh[tx * 8 + c2 * 2 + 1], 0.f);
            hv[r][c2 * 2]     = valid ? h0 : 0.f;
            hv[r][c2 * 2 + 1] = valid ? h1 : 0.f;
        }
        if (valid) {
#pragma unroll
            for (int j = 0; j < 8; j++) {
                csum[j] += hv[r][j];
                csq[j]  += hv[r][j] * hv[r][j];
            }
        }
    }
    // block-level column reduction through smem (reuse Ws), then 2 atomics/col
    float* red = &Ws[0][0];
#pragma unroll
    for (int j = 0; j < 8; j++) red[ty * 264 + tx * 8 + j] = csum[j];
    __syncthreads();
    {
        float s = 0.f;
#pragma unroll
        for (int t = 0; t < 8; t++) s += red[t * 264 + tid];
        redF1(&g_bnstats[tid], s);
    }
    __syncthreads();
#pragma unroll
    for (int j = 0; j < 8; j++) red[ty * 264 + tx * 8 + j] = csq[j];
    __syncthreads();
    {
        float q = 0.f;
#pragma unroll
        for (int t = 0; t < 8; t++) q += red[t * 264 + tid];
        redF1(&g_bnstats[256 + tid], q);
    }

    // per-graph raw pooling: graph_id is sorted, so a block spans few graphs
    if (tid == 0) {
        int lo = gids[0], hi = lo;
#pragma unroll 1
        for (int i = 1; i < 64; i++)
            if (gids[i] >= 0) hi = gids[i];
        grange[0] = lo; grange[1] = hi;
    }
    __syncthreads();
    int glo = grange[0], ghi = grange[1];
#pragma unroll 1
    for (int g = glo; g <= ghi; g++) {
        float s[8];
#pragma unroll
        for (int j = 0; j < 8; j++) s[j] = 0.f;
#pragma unroll
        for (int r = 0; r < 8; r++) {
            if (gids[ty * 8 + r] == g) {
#pragma unroll
                for (int j = 0; j < 8; j++) s[j] += hv[r][j];
            }
        }
        __syncthreads();
#pragma unroll
        for (int j = 0; j < 8; j++) red[ty * 264 + tx * 8 + j] = s[j];
        __syncthreads();
        float t = 0.f;
#pragma unroll
        for (int q = 0; q < 8; q++) t += red[q * 264 + tid];
        redF1(&g_poolraw[g * HID + tid], t);
    }
}

// ---------------- K2b: fold BN stats into per-column scale/shift ----------------
__global__ void bn_scale_kernel(const float* __restrict__ gamma,
                                const float* __restrict__ beta) {
    int c = threadIdx.x;
    float mean = g_bnstats[c] * (1.0f / NN);
    float var  = g_bnstats[256 + c] * (1.0f / NN) - mean * mean;
    float sc = gamma[c] * rsqrtf(var + BN_EPS);
    g_bnstats[1536 + c] = sc;
    g_bnstats[1792 + c] = beta[c] - mean * sc;
}

// ---------------- K4: head pass 1  z1 = relu(pooled @ W_lp + b) + stats ------------
// pooled[g][c] = poolraw[g][c]*sc[c] + cnt[g]*sh[c]  (BN-apply folded into pooling)
__global__ __launch_bounds__(HID) void lp1_kernel(const float* __restrict__ W_lp,
                                                  const float* __restrict__ b_lp) {
    __shared__ float row[HID];
    int g = blockIdx.x, c = threadIdx.x;
    float cntf = (float)g_cnt[g];
    row[c] = fmaf(g_poolraw[g * HID + c], g_bnstats[1536 + c],
                  cntf * g_bnstats[1792 + c]);
    __syncthreads();
    float acc = b_lp[c];
#pragma unroll 8
    for (int k = 0; k < HID; k++) acc = fmaf(row[k], __ldg(&W_lp[k * HID + c]), acc);
    float r = fmaxf(acc, 0.f);
    g_z1[g * HID + c] = r;
    atomicAdd(&g_bnstats[512 + c], r);
    atomicAdd(&g_bnstats[768 + c], r * r);
}

// ---------------- K5: BN(z1) -> p (output), then z2 = relu(p @ W_lp + b) + stats ----
__global__ __launch_bounds__(HID) void lp2_kernel(const float* __restrict__ W_lp,
                                                  const float* __restrict__ b_lp,
                                                  const float* __restrict__ gamma,
                                                  const float* __restrict__ beta,
                                                  float* __restrict__ out_p) {
    __shared__ float row[HID];
    int g = blockIdx.x, c = threadIdx.x;
    float r = g_z1[g * HID + c];
    float mean = g_bnstats[512 + c] * (1.f / GG);
    float var  = g_bnstats[768 + c] * (1.f / GG) - mean * mean;
    float p = (r - mean) * rsqrtf(var + BN_EPS) * gamma[c] + beta[c];
    out_p[g * HID + c] = p;
    row[c] = p;
    __syncthreads();
    float acc = b_lp[c];
#pragma unroll 8
    for (int k = 0; k < HID; k++) acc = fmaf(row[k], __ldg(&W_lp[k * HID + c]), acc);
    float r2 = fmaxf(acc, 0.f);
    g_z2[g * HID + c] = r2;
    atomicAdd(&g_bnstats[1024 + c], r2);
    atomicAdd(&g_bnstats[1280 + c], r2 * r2);
}

// ---------------- K6: BN(z2) + log_softmax -> output ----------------
__global__ __launch_bounds__(HID) void lp3_kernel(const float* __restrict__ gamma,
                                                  const float* __restrict__ beta,
                                                  float* __restrict__ out) {
    __shared__ float buf[HID];
    int g = blockIdx.x, c = threadIdx.x;
    float r = g_z2[g * HID + c];
    float mean = g_bnstats[1024 + c] * (1.f / GG);
    float var  = g_bnstats[1280 + c] * (1.f / GG) - mean * mean;
    float o = (r - mean) * rsqrtf(var + BN_EPS) * gamma[c] + beta[c];
    buf[c] = o;
    __syncthreads();
    for (int s = 128; s > 0; s >>= 1) {
        if (c < s) buf[c] = fmaxf(buf[c], buf[c + s]);
        __syncthreads();
    }
    float m = buf[0];
    __syncthreads();
    float e = expf(o - m);
    buf[c] = e;
    __syncthreads();
    for (int s = 128; s > 0; s >>= 1) {
        if (c < s) buf[c] += buf[c + s];
        __syncthreads();
    }
    float lse = logf(buf[0]);
    out[g * HID + c] = o - m - lse;
}

// ---------------- launch ----------------
extern "C" void kernel_launch(void* const* d_in, const int* in_sizes, int n_in,
                              void* d_out, int out_size) {
    const float* feat       = (const float*)d_in[0];
    const float* W_self     = (const float*)d_in[1];
    const float* W_neigh    = (const float*)d_in[2];
    const float* b_conv     = (const float*)d_in[3];
    const float* gamma_conv = (const float*)d_in[4];
    const float* beta_conv  = (const float*)d_in[5];
    const float* W_lp       = (const float*)d_in[6];
    const float* b_lp       = (const float*)d_in[7];
    const float* gamma_lp   = (const float*)d_in[8];
    const float* beta_lp    = (const float*)d_in[9];
    const int*   src        = (const int*)d_in[10];
    const int*   dst        = (const int*)d_in[11];
    const int*   graph_id   = (const int*)d_in[12];
    float* out = (float*)d_out;

    float* out_p;
    if (out_size >= 2 * GG * HID) {
        out_p = out + GG * HID;
    } else {
        void* pp = nullptr;
        cudaGetSymbolAddress(&pp, g_p);
        out_p = (float*)pp;
    }

    zero_kernel<<<(NN * IND / 4 + 255) / 256, 256>>>();
    count_kernel<<<128, 1024>>>(graph_id);
    scatter_kernel<<<(EE * 32 + 255) / 256, 256>>>(feat, src, dst);
    conv_gemm_kernel<<<(NN + 63) / 64, 256>>>(feat, W_self, W_neigh, b_conv, graph_id);
    bn_scale_kernel<<<1, HID>>>(gamma_conv, beta_conv);
    lp1_kernel<<<GG, HID>>>(W_lp, b_lp);
    lp2_kernel<<<GG, HID>>>(W_lp, b_lp, gamma_lp, beta_lp, out_p);
    lp3_kernel<<<GG, HID>>>(gamma_lp, beta_lp, out);
}